// round 7
// baseline (speedup 1.0000x reference)
#include <cuda_runtime.h>
#include <cuda_bf16.h>

#define TOKENS 32768
#define DMODEL 2048
#define NEXP   64
#define TBLK   128
#define KC     32
#define NCHUNK (DMODEL / KC)   // 64
#define NTH    256
#define XP     40              // smem pitch in bf16 elems (80B)
#define LG_LD  68

// stage byte offsets (x tiles only now)
#define XH_OFF 0
#define XL_OFF 10240
#define STAGE  20480
#define SMEM_DYN (2 * STAGE)   // 40 KB; logits epilogue needs 34.8 KB < this

typedef unsigned int u32;
typedef unsigned long long u64;

// Precomputed w B-fragments: [chunk][ks][ntile(8)][hl][lane] -> (b0,b1) packed u64
__device__ u64 g_wfrag[NCHUNK * 2 * 8 * 2 * 32];   // 512 KB

static __device__ __forceinline__ u32 smem_u32(const void* p) {
    u32 a;
    asm("{ .reg .u64 t; cvta.to.shared.u64 t, %1; cvt.u32.u64 %0, t; }" : "=r"(a) : "l"(p));
    return a;
}

// fp32 -> (bf16_hi, bf16_lo) split of 4 values, packed as u64 pairs
static __device__ __forceinline__ void split4(float4 v, u64& hi, u64& lo) {
    __nv_bfloat162 h01 = __float22bfloat162_rn(make_float2(v.x, v.y));
    __nv_bfloat162 h23 = __float22bfloat162_rn(make_float2(v.z, v.w));
    float2 f01 = __bfloat1622float2(h01);
    float2 f23 = __bfloat1622float2(h23);
    __nv_bfloat162 l01 = __float22bfloat162_rn(make_float2(v.x - f01.x, v.y - f01.y));
    __nv_bfloat162 l23 = __float22bfloat162_rn(make_float2(v.z - f23.x, v.w - f23.y));
    u32 a = *reinterpret_cast<u32*>(&h01);
    u32 b = *reinterpret_cast<u32*>(&h23);
    u32 c = *reinterpret_cast<u32*>(&l01);
    u32 d = *reinterpret_cast<u32*>(&l23);
    hi = (u64)a | ((u64)b << 32);
    lo = (u64)c | ((u64)d << 32);
}

#define LDSM_X4(R, addr)                                                      \
    asm volatile("ldmatrix.sync.aligned.m8n8.x4.shared.b16 {%0,%1,%2,%3}, [%4];" \
        : "=r"((R)[0]), "=r"((R)[1]), "=r"((R)[2]), "=r"((R)[3]) : "r"(addr))

#define MMA_BF16(C, A, B0, B1)                                                \
    asm volatile("mma.sync.aligned.m16n8k16.row.col.f32.bf16.bf16.f32 "       \
        "{%0,%1,%2,%3}, {%4,%5,%6,%7}, {%8,%9}, {%0,%1,%2,%3};"               \
        : "+f"((C)[0]), "+f"((C)[1]), "+f"((C)[2]), "+f"((C)[3])              \
        : "r"((A)[0]), "r"((A)[1]), "r"((A)[2]), "r"((A)[3]), "r"(B0), "r"(B1))

// ---- pre-kernel: build w B-fragments (PTX m16n8k16 B layout) ----
// idx = ch*1024 + ks*512 + nt*64 + hl*32 + lane  (== linear g_wfrag index)
__global__ void wsplit_kernel(const float* __restrict__ w) {
    int idx  = blockIdx.x * blockDim.x + threadIdx.x;
    int lane = idx & 31;
    int hl   = (idx >> 5) & 1;
    int nt   = (idx >> 6) & 7;
    int ks   = (idx >> 9) & 1;
    int ch   = idx >> 10;
    int n  = nt * 8 + (lane >> 2);
    int k0 = ch * KC + ks * 16 + (lane & 3) * 2;
    const float* wr = w + (size_t)n * DMODEL + k0;
    float2 p0 = *(const float2*)(wr);       // b0: k0, k0+1
    float2 p1 = *(const float2*)(wr + 8);   // b1: k0+8, k0+9
    __nv_bfloat162 h0 = __float22bfloat162_rn(p0);
    __nv_bfloat162 h1 = __float22bfloat162_rn(p1);
    u32 r0, r1;
    if (hl == 0) {
        r0 = *reinterpret_cast<u32*>(&h0);
        r1 = *reinterpret_cast<u32*>(&h1);
    } else {
        float2 f0 = __bfloat1622float2(h0);
        float2 f1 = __bfloat1622float2(h1);
        __nv_bfloat162 l0 = __float22bfloat162_rn(make_float2(p0.x - f0.x, p0.y - f0.y));
        __nv_bfloat162 l1 = __float22bfloat162_rn(make_float2(p1.x - f1.x, p1.y - f1.y));
        r0 = *reinterpret_cast<u32*>(&l0);
        r1 = *reinterpret_cast<u32*>(&l1);
    }
    g_wfrag[idx] = (u64)r0 | ((u64)r1 << 32);
}

__global__ __launch_bounds__(NTH, 2)
void router_hmma_kernel(const float* __restrict__ x,
                        float* __restrict__ out)
{
    extern __shared__ char dsm[];
    __shared__ float inv_s[TBLK];

    const int tid = threadIdx.x;
    const int wid = tid >> 5;
    const int lid = tid & 31;
    const int t0  = blockIdx.x * TBLK;
    const u32 dsm_b = smem_u32(dsm);

    // ---- global load geometry (x only) ----
    const int gr = tid >> 3;            // 0..31
    const int gc = tid & 7;             // float4 col in chunk
    const float* xbase = x + (size_t)(t0 + gr) * DMODEL + gc * 4;
    const u32 sts_off = (u32)((gr * XP + gc * 4) * 2);

    // ---- warp tile: 32 tokens x 32 experts ----
    const int wtok0 = (wid >> 1) * 32;
    const int wnt0  = (wid & 1) * 4;    // first of 4 n-tiles (8 experts each)

    // A ldmatrix address components
    const int arow = (lid & 7) + ((lid >> 3) & 1) * 8;
    const int acol = ((lid >> 4) & 1) * 8;
    const u32 a_off = (u32)(((wtok0 + arow) * XP + acol) * 2);

    // per-warp wfrag base (u64 index): + (ks*8 + nt)*2*32 + hl*32
    const u64* wf_lane = g_wfrag + (size_t)wnt0 * 64 + lid;

    float acc[2][4][4];
    #pragma unroll
    for (int mt = 0; mt < 2; mt++)
        #pragma unroll
        for (int nt = 0; nt < 4; nt++)
            #pragma unroll
            for (int c = 0; c < 4; c++)
                acc[mt][nt][c] = 0.0f;

    float4 xr[4];

    // ---- prologue: chunk 0 -> stage 0; prefetch chunk 1 ----
    #pragma unroll
    for (int i = 0; i < 4; i++) xr[i] = *(const float4*)(xbase + (size_t)i * 32 * DMODEL);
    {
        char* st = dsm;
        #pragma unroll
        for (int i = 0; i < 4; i++) {
            u64 hi, lo; split4(xr[i], hi, lo);
            u32 o = sts_off + i * 32 * XP * 2;
            *(u64*)(st + XH_OFF + o) = hi;
            *(u64*)(st + XL_OFF + o) = lo;
        }
    }
    #pragma unroll
    for (int i = 0; i < 4; i++) xr[i] = *(const float4*)(xbase + KC + (size_t)i * 32 * DMODEL);

    for (int ch = 0; ch < NCHUNK; ++ch) {
        // wfrag loads for this chunk (coalesced LDG.64) — issued before the
        // barrier so their latency hides under the sync + STS phase.
        u64 wreg[2][4][2];
        {
            const u64* wfc = wf_lane + (size_t)ch * 1024;
            #pragma unroll
            for (int ks = 0; ks < 2; ks++)
                #pragma unroll
                for (int nt = 0; nt < 4; nt++) {
                    wreg[ks][nt][0] = wfc[(ks * 8 + nt) * 64];
                    wreg[ks][nt][1] = wfc[(ks * 8 + nt) * 64 + 32];
                }
        }

        __syncthreads();

        // STS next x stage from prefetched regs
        if (ch + 1 < NCHUNK) {
            char* st = dsm + ((ch + 1) & 1) * STAGE;
            #pragma unroll
            for (int i = 0; i < 4; i++) {
                u64 hi, lo; split4(xr[i], hi, lo);
                u32 o = sts_off + i * 32 * XP * 2;
                *(u64*)(st + XH_OFF + o) = hi;
                *(u64*)(st + XL_OFF + o) = lo;
            }
        }
        // prefetch x chunk ch+2
        if (ch + 2 < NCHUNK) {
            const int k0 = (ch + 2) * KC;
            #pragma unroll
            for (int i = 0; i < 4; i++)
                xr[i] = *(const float4*)(xbase + k0 + (size_t)i * 32 * DMODEL);
        }

        // compute current stage
        const u32 sb = dsm_b + (ch & 1) * STAGE;
        const u32 ah_b = sb + XH_OFF + a_off;
        const u32 al_b = sb + XL_OFF + a_off;

        #pragma unroll
        for (int ks = 0; ks < 2; ks++) {
            const u32 ko = ks * 32;   // 16 elems * 2B
            u32 ah[8], al[8];
            #pragma unroll
            for (int mt = 0; mt < 2; mt++) {
                LDSM_X4(ah + mt * 4, ah_b + mt * (16 * XP * 2) + ko);
                LDSM_X4(al + mt * 4, al_b + mt * (16 * XP * 2) + ko);
            }
            #pragma unroll
            for (int mt = 0; mt < 2; mt++)
                #pragma unroll
                for (int nt = 0; nt < 4; nt++) {
                    u32 bh0 = (u32)wreg[ks][nt][0];
                    u32 bh1 = (u32)(wreg[ks][nt][0] >> 32);
                    u32 bl0 = (u32)wreg[ks][nt][1];
                    u32 bl1 = (u32)(wreg[ks][nt][1] >> 32);
                    MMA_BF16(acc[mt][nt], ah + mt * 4, bh0, bh1);   // hi*hi
                    MMA_BF16(acc[mt][nt], al + mt * 4, bh0, bh1);   // lo*hi
                    MMA_BF16(acc[mt][nt], ah + mt * 4, bl0, bl1);   // hi*lo
                }
        }
    }

    // ---- epilogue: accs -> smem logits (stage memory dead) ----
    __syncthreads();
    float* logits = (float*)dsm;
    {
        const int crow = lid >> 2;
        const int ccol = (lid & 3) * 2;
        const int wexp0 = wnt0 * 8;
        #pragma unroll
        for (int mt = 0; mt < 2; mt++)
            #pragma unroll
            for (int nt = 0; nt < 4; nt++) {
                int tok = wtok0 + mt * 16 + crow;
                int ex  = wexp0 + nt * 8 + ccol;
                *(float2*)&logits[tok * LG_LD + ex] =
                    make_float2(acc[mt][nt][0], acc[mt][nt][1]);
                *(float2*)&logits[(tok + 8) * LG_LD + ex] =
                    make_float2(acc[mt][nt][2], acc[mt][nt][3]);
            }
    }
    __syncthreads();

    if (tid < TBLK) {
        const int t = tid;
        float* row = &logits[t * LG_LD];

        float m1 = -3.4e38f, m2 = -3.4e38f;
        int   i1 = 0,        i2 = 0;
        #pragma unroll
        for (int e = 0; e < NEXP; e++) {
            float v = row[e];
            if (v > m1)      { m2 = m1; i2 = i1; m1 = v; i1 = e; }
            else if (v > m2) { m2 = v; i2 = e; }
        }

        float s = 0.0f;
        #pragma unroll
        for (int e = 0; e < NEXP; e++) {
            float ev = __expf(row[e] - m1);
            row[e] = ev;
            s += ev;
        }
        inv_s[t] = 1.0f / s;

        float e2v = __expf(m2 - m1);
        float g1  = 1.0f / (1.0f + e2v);

        int gt = t0 + t;
        out[2 * gt + 0] = g1;
        out[2 * gt + 1] = e2v * g1;
        float* oidx = out + (size_t)2 * TOKENS;
        oidx[2 * gt + 0] = (float)i1;
        oidx[2 * gt + 1] = (float)i2;
    }
    __syncthreads();

    float* oprob = out + (size_t)4 * TOKENS;
    for (int f = tid; f < TBLK * (NEXP / 4); f += NTH) {
        int r = f >> 4, c4 = f & 15;
        float4 ev = *(const float4*)&logits[r * LG_LD + c4 * 4];
        float inv = inv_s[r];
        float4 p = make_float4(ev.x * inv, ev.y * inv, ev.z * inv, ev.w * inv);
        *(float4*)&oprob[(size_t)(t0 + r) * NEXP + c4 * 4] = p;
    }
}

extern "C" void kernel_launch(void* const* d_in, const int* in_sizes, int n_in,
                              void* d_out, int out_size) {
    const float* x = (const float*)d_in[0];
    const float* w = (const float*)d_in[1];
    float* out = (float*)d_out;
    wsplit_kernel<<<256, 256>>>(w);
    cudaFuncSetAttribute(router_hmma_kernel,
                         cudaFuncAttributeMaxDynamicSharedMemorySize, SMEM_DYN);
    router_hmma_kernel<<<TOKENS / TBLK, NTH, SMEM_DYN>>>(x, out);
}